// round 13
// baseline (speedup 1.0000x reference)
#include <cuda_runtime.h>
#include <cuda_fp16.h>
#include <cstdint>

namespace {
constexpr int Bn = 4096, Tn = 32, Xn = 256, En = 32, Hn = 512, Ln = 2;
constexpr int BM = 32;     // rows per CTA
constexpr int BK = 32;     // K columns per chunk (two k16 slabs)
constexpr int NT = 256;    // 8 warps (warpN 0..7)
constexpr int ST = 3;      // TMA ring stages
constexpr int CHUNK_U32  = Hn * 16;            // 8192 u32 (fp16x2) = 32 KB
constexpr int CHUNK_BYTES = CHUNK_U32 * 4;
constexpr int ABUF_U32 = 32 * 2 * 32 * 4;      // 8192 u32 = 32 KB (32 k16 x 2 mt)
constexpr int SMEM_BYTES = (ABUF_U32 + ST * CHUNK_U32) * 4;   // 32768 + 98304 = 131072
constexpr int CPE = (Tn + Xn) / BK + Ln * (Hn / BK);          // 9 + 32 = 41
}

// Weights as fp16x2, B-fragment-packed chunk stream (BK=32: two k16 slabs):
// u32 f -> s = f>>12 (k16 slab), col = (f&4095)>>3, q = f&7, t = q>>1,
// half = q&1; value = {W[k0+s*16+half*8+2t][col], W[...+1][col]} (lo,hi).
__device__ uint32_t wscratch[(size_t)En * CPE * CHUNK_U32];

__device__ __forceinline__ uint32_t pack_h2(float lo, float hi) {
    uint32_t r;
    asm("cvt.rn.f16x2.f32 %0, %1, %2;" : "=r"(r) : "f"(hi), "f"(lo));
    return r;
}

// fp16-element index into the A-frag-packed buffer (as __half*), BM=32.
__device__ __forceinline__ int hidx(int r, int c) {
    const int u = ((c >> 4) * 2 + (r >> 4)) * 128
                + ((r & 7) * 4 + ((c & 7) >> 1)) * 4
                + ((r >> 3) & 1) + 2 * ((c >> 3) & 1);
    return u * 2 + (c & 1);
}

__device__ __forceinline__ void mma_f16(float c[4],
                                        uint32_t a0, uint32_t a1, uint32_t a2, uint32_t a3,
                                        uint32_t b0, uint32_t b1) {
    asm volatile(
        "mma.sync.aligned.m16n8k16.row.col.f32.f16.f16.f32 "
        "{%0,%1,%2,%3}, {%4,%5,%6,%7}, {%8,%9}, {%0,%1,%2,%3};\n"
        : "+f"(c[0]), "+f"(c[1]), "+f"(c[2]), "+f"(c[3])
        : "r"(a0), "r"(a1), "r"(a2), "r"(a3), "r"(b0), "r"(b1));
}

__device__ __forceinline__ void mbar_init(uint32_t mbar, uint32_t cnt) {
    asm volatile("mbarrier.init.shared.b64 [%0], %1;" :: "r"(mbar), "r"(cnt) : "memory");
}
__device__ __forceinline__ void mbar_expect_tx(uint32_t mbar, uint32_t bytes) {
    asm volatile("mbarrier.arrive.expect_tx.shared.b64 _, [%0], %1;"
                 :: "r"(mbar), "r"(bytes) : "memory");
}
__device__ __forceinline__ void bulk_g2s(uint32_t dst, const void* src,
                                         uint32_t bytes, uint32_t mbar) {
    asm volatile(
        "cp.async.bulk.shared::cta.global.mbarrier::complete_tx::bytes "
        "[%0], [%1], %2, [%3];"
        :: "r"(dst), "l"(src), "r"(bytes), "r"(mbar) : "memory");
}
__device__ __forceinline__ void mbar_wait(uint32_t mbar, uint32_t phase) {
    uint32_t done;
    do {
        asm volatile(
            "{\n\t.reg .pred p;\n\t"
            "mbarrier.try_wait.parity.acquire.cta.shared::cta.b64 p, [%1], %2, 0x989680;\n\t"
            "selp.b32 %0, 1, 0, p;\n\t}"
            : "=r"(done) : "r"(mbar), "r"(phase) : "memory");
    } while (!done);
}

// ---------- prep: fp16-pack weights into B-frag chunk stream (BK=32) ---------
__global__ void mnre_prep(const float* __restrict__ W1t, const float* __restrict__ W1x,
                          const float* __restrict__ Wh) {
    const int blk = blockIdx.x;              // e*CPE + cg
    const int e  = blk / CPE;
    const int cg = blk % CPE;
    uint32_t* dst = wscratch + (size_t)blk * CHUNK_U32;
    for (int f = threadIdx.x; f < CHUNK_U32; f += blockDim.x) {
        const int s    = f >> 12;            // k16 slab 0..1
        const int rem  = f & 4095;
        const int col  = rem >> 3;
        const int q    = rem & 7;
        const int t    = q >> 1;
        const int half = q & 1;
        const int koff = s * 16 + half * 8 + t * 2;
        float v0, v1;
        if (cg < 9) {
            const int k = cg * BK + koff;
            auto ld = [&](int kk) -> float {
                return (kk < Tn) ? W1t[(size_t)(e * Tn + kk) * Hn + col]
                                 : W1x[(size_t)(e * Xn + (kk - Tn)) * Hn + col];
            };
            v0 = ld(k); v1 = ld(k + 1);
        } else {
            const int l = (cg < 25) ? 0 : 1;
            const int k = ((cg < 25) ? (cg - 9) : (cg - 25)) * BK + koff;
            const float* W = Wh + ((size_t)(l * En + e) * Hn + k) * Hn + col;
            v0 = W[0]; v1 = W[Hn];
        }
        dst[f] = pack_h2(v0, v1);
    }
}

// ---------- main fused kernel ------------------------------------------------
__global__ __launch_bounds__(NT, 2)
void mnre_h32(const float* __restrict__ theta, const float* __restrict__ x,
              const int*   __restrict__ masks,
              const float* __restrict__ b1,  const float* __restrict__ a1,
              const float* __restrict__ bh,  const float* __restrict__ ah,
              const float* __restrict__ Wo,  const float* __restrict__ bo,
              float* __restrict__ out)
{
    extern __shared__ uint32_t smem[];
    uint32_t* abuf = smem;                 // A-frag-packed fp16 activations
    uint32_t* wrg  = smem + ABUF_U32;      // ST x CHUNK_U32 weight ring
    __shared__ alignas(8) unsigned long long mbars[ST];

    const int e    = blockIdx.y;
    const int m0   = blockIdx.x * BM;
    const int tid  = threadIdx.x;
    const int lane = tid & 31;
    const int wy   = tid >> 5;         // warpN 0..7
    const int g    = lane >> 2;        // 0..7
    const int t    = lane & 3;         // 0..3
    const int nbase = wy * 64;

    uint32_t bars[ST];
    #pragma unroll
    for (int i = 0; i < ST; i++)
        bars[i] = (uint32_t)__cvta_generic_to_shared(&mbars[i]);
    const uint32_t* wexp = wscratch + (size_t)e * CPE * CHUNK_U32;
    const uint32_t wrg0 = (uint32_t)__cvta_generic_to_shared(wrg);

    if (tid == 0) {
        #pragma unroll
        for (int i = 0; i < ST; i++) mbar_init(bars[i], 1);
        asm volatile("fence.proxy.async.shared::cta;" ::: "memory");
    }
    __syncthreads();

    // prologue: chunks 0..ST-2 in flight
    if (tid == 0) {
        #pragma unroll
        for (int i = 0; i < ST - 1; i++) {
            mbar_expect_tx(bars[i], CHUNK_BYTES);
            bulk_g2s(wrg0 + i * CHUNK_BYTES, wexp + (size_t)i * CHUNK_U32,
                     CHUNK_BYTES, bars[i]);
        }
    }

    // ---- stage inputs (fp16) into A-frag-packed abuf
    __half* hbuf = reinterpret_cast<__half*>(abuf);
    #pragma unroll
    for (int it = 0; it < (BM * Tn) / NT; it++) {
        const int i = tid + it * NT;
        const int m = i >> 5, k = i & 31;
        const float v = theta[(size_t)(m0 + m) * Tn + k] * (float)masks[e * Tn + k];
        hbuf[hidx(m, k)] = __float2half_rn(v);
    }
    #pragma unroll 4
    for (int it = 0; it < (BM * Xn) / NT; it++) {
        const int i = tid + it * NT;
        const int m = i >> 8, k = i & 255;
        hbuf[hidx(m, Tn + k)] = __float2half_rn(x[(size_t)(m0 + m) * Xn + k]);
    }

    float c[2][8][4];   // [mtile][nblock][frag]
    int qg = 0;         // global chunk index 0..CPE-1

    for (int layer = 0; layer < 1 + Ln; layer++) {
        const int K   = (layer == 0) ? (Tn + Xn) : Hn;
        const int nch = K / BK;
        const float* bias;
        const float* slope;
        if (layer == 0) {
            bias  = b1 + (size_t)e * Hn;
            slope = a1 + (size_t)e * Hn;
        } else {
            const int l = layer - 1;
            bias  = bh + (size_t)(l * En + e) * Hn;
            slope = ah + (size_t)(l * En + e) * Hn;
        }

        // init accumulators with bias
        #pragma unroll
        for (int nb = 0; nb < 8; nb++) {
            const int col0 = nbase + nb * 8 + 2 * t;
            const float bv0 = bias[col0], bv1 = bias[col0 + 1];
            #pragma unroll
            for (int mt = 0; mt < 2; mt++) {
                c[mt][nb][0] = bv0; c[mt][nb][1] = bv1;
                c[mt][nb][2] = bv0; c[mt][nb][3] = bv1;
            }
        }

        for (int ci = 0; ci < nch; ci++, qg++) {
            __syncthreads();   // all warps done with stage (qg+ST-1)%ST's old data

            // continuous prefetch across layer boundaries
            if (tid == 0 && qg + ST - 1 < CPE) {
                const int sn = (qg + ST - 1) % ST;
                mbar_expect_tx(bars[sn], CHUNK_BYTES);
                bulk_g2s(wrg0 + sn * CHUNK_BYTES,
                         wexp + (size_t)(qg + ST - 1) * CHUNK_U32,
                         CHUNK_BYTES, bars[sn]);
            }

            const int sc = qg % ST;
            mbar_wait(bars[sc], (qg / ST) & 1u);
            const uint32_t* w = wrg + sc * CHUNK_U32;

            #pragma unroll
            for (int s = 0; s < 2; s++) {          // two k16 slabs per chunk
                const int k16 = ci * 2 + s;
                // A frags: one LDS.128 per m16 tile (4 HMMA A-regs)
                uint32_t a[2][4];
                #pragma unroll
                for (int mt = 0; mt < 2; mt++) {
                    const uint4 av = *reinterpret_cast<const uint4*>(
                        abuf + ((k16 * 2 + mt) * 32 + lane) * 4);
                    a[mt][0] = av.x; a[mt][1] = av.y; a[mt][2] = av.z; a[mt][3] = av.w;
                }
                // B frags: one LDS.64 per nb (2 HMMA B-regs)
                const uint32_t* ws = w + s * 4096;
                #pragma unroll
                for (int nb = 0; nb < 8; nb++) {
                    const int col = nbase + nb * 8 + g;
                    const uint2 bv = *reinterpret_cast<const uint2*>(
                        ws + (col * 4 + t) * 2);
                    mma_f16(c[0][nb], a[0][0], a[0][1], a[0][2], a[0][3], bv.x, bv.y);
                    mma_f16(c[1][nb], a[1][0], a[1][1], a[1][2], a[1][3], bv.x, bv.y);
                }
            }
        }

        __syncthreads();   // all abuf reads for this layer done
        // epilogue: PReLU, fp16-pack, write A-frag-packed (in place)
        #pragma unroll
        for (int nb = 0; nb < 8; nb++) {
            const int col0 = nbase + nb * 8 + 2 * t;
            const float s0 = slope[col0], s1 = slope[col0 + 1];
            const int kb = wy * 4 + (nb >> 1);
            const int h  = nb & 1;
            #pragma unroll
            for (int mt = 0; mt < 2; mt++) {
                float v0 = c[mt][nb][0]; v0 = (v0 >= 0.f) ? v0 : s0 * v0;
                float v1 = c[mt][nb][1]; v1 = (v1 >= 0.f) ? v1 : s1 * v1;
                float v2 = c[mt][nb][2]; v2 = (v2 >= 0.f) ? v2 : s0 * v2;
                float v3 = c[mt][nb][3]; v3 = (v3 >= 0.f) ? v3 : s1 * v3;
                uint2 o;
                o.x = pack_h2(v0, v1);   // row g     (a0/a2 slot)
                o.y = pack_h2(v2, v3);   // row g + 8 (a1/a3 slot)
                *reinterpret_cast<uint2*>(
                    abuf + (kb * 2 + mt) * 128 + (g * 4 + t) * 4 + 2 * h) = o;
            }
        }
    }
    __syncthreads();

    // ---- output: dot with Wo, shfl reduce (fp32)
    {
        const float* wo = Wo + (size_t)e * Hn;
        const int r0 = wy * 4;   // 8 warps x 4 rows = 32
        float partial[4] = {0.f, 0.f, 0.f, 0.f};
        #pragma unroll
        for (int j = 0; j < 16; j++) {
            const int cidx = lane + j * 32;
            const float wv = wo[cidx];
            #pragma unroll
            for (int r = 0; r < 4; r++)
                partial[r] = fmaf(__half2float(hbuf[hidx(r0 + r, cidx)]), wv, partial[r]);
        }
        const float bov = bo[e];
        #pragma unroll
        for (int r = 0; r < 4; r++) {
            float s = partial[r];
            #pragma unroll
            for (int off = 16; off > 0; off >>= 1)
                s += __shfl_xor_sync(0xffffffffu, s, off);
            if (lane == 0)
                out[(size_t)(m0 + r0 + r) * En + e] = s + bov;
        }
    }
}

extern "C" void kernel_launch(void* const* d_in, const int* in_sizes, int n_in,
                              void* d_out, int out_size) {
    const float* theta = (const float*)d_in[0];
    const float* x     = (const float*)d_in[1];
    const int*   masks = (const int*)  d_in[2];
    const float* W1t   = (const float*)d_in[3];
    const float* W1x   = (const float*)d_in[4];
    const float* b1    = (const float*)d_in[5];
    const float* a1    = (const float*)d_in[6];
    const float* Wh    = (const float*)d_in[7];
    const float* bh    = (const float*)d_in[8];
    const float* ah    = (const float*)d_in[9];
    const float* Wo    = (const float*)d_in[10];
    const float* bo    = (const float*)d_in[11];
    float* out = (float*)d_out;

    // 1) fp16-pack weights into the B-frag chunk stream (BK=32)
    mnre_prep<<<En * CPE, 256>>>(W1t, W1x, Wh);

    // 2) fused fp16-HMMA MLP, BM=32, 2 CTAs/SM, BK=32 chunks
    cudaFuncSetAttribute(mnre_h32, cudaFuncAttributeMaxDynamicSharedMemorySize,
                         SMEM_BYTES);
    dim3 grid(Bn / BM, En);   // 128 x 32 = 4096 CTAs
    mnre_h32<<<grid, NT, SMEM_BYTES>>>(theta, x, masks, b1, a1,
                                       bh, ah, Wo, bo, out);
}

// round 16
// speedup vs baseline: 1.3005x; 1.3005x over previous
#include <cuda_runtime.h>
#include <cuda_fp16.h>
#include <cstdint>

namespace {
constexpr int Bn = 4096, Tn = 32, Xn = 256, En = 32, Hn = 512, Ln = 2;
constexpr int BM = 32;     // rows per CTA
constexpr int BK = 16;     // K columns per chunk (one k16 slab)
constexpr int NT = 256;    // 8 warps (warpN 0..7)
constexpr int ST = 4;      // TMA ring stages
constexpr int CHUNK_U32  = Hn * 8;             // 4096 u32 (fp16x2) = 16 KB
constexpr int CHUNK_BYTES = CHUNK_U32 * 4;
constexpr int ABUF_U32 = 32 * 2 * 32 * 4;      // 8192 u32 = 32 KB (32 k16 x 2 mt)
constexpr int SMEM_BYTES = (ABUF_U32 + ST * CHUNK_U32) * 4;   // 32768 + 65536 = 98304
constexpr int CPE = (Tn + Xn) / BK + Ln * (Hn / BK);          // 18 + 64 = 82
}

// Weights as fp16x2, B-fragment-packed chunk stream:
// u32 f in chunk -> col = f>>3, q = f&7, t = q>>1, half = q&1,
// value = {W[k0+half*8+2t][col], W[k0+half*8+2t+1][col]} (lo,hi).
__device__ uint32_t wscratch[(size_t)En * CPE * CHUNK_U32];

__device__ __forceinline__ uint32_t pack_h2(float lo, float hi) {
    uint32_t r;
    asm("cvt.rn.f16x2.f32 %0, %1, %2;" : "=r"(r) : "f"(hi), "f"(lo));
    return r;
}

// fp16-element index into the A-frag-packed buffer (as __half*), BM=32.
__device__ __forceinline__ int hidx(int r, int c) {
    const int u = ((c >> 4) * 2 + (r >> 4)) * 128
                + ((r & 7) * 4 + ((c & 7) >> 1)) * 4
                + ((r >> 3) & 1) + 2 * ((c >> 3) & 1);
    return u * 2 + (c & 1);
}

__device__ __forceinline__ void mma_f16(float c[4],
                                        uint32_t a0, uint32_t a1, uint32_t a2, uint32_t a3,
                                        uint32_t b0, uint32_t b1) {
    asm volatile(
        "mma.sync.aligned.m16n8k16.row.col.f32.f16.f16.f32 "
        "{%0,%1,%2,%3}, {%4,%5,%6,%7}, {%8,%9}, {%0,%1,%2,%3};\n"
        : "+f"(c[0]), "+f"(c[1]), "+f"(c[2]), "+f"(c[3])
        : "r"(a0), "r"(a1), "r"(a2), "r"(a3), "r"(b0), "r"(b1));
}

__device__ __forceinline__ void mbar_init(uint32_t mbar, uint32_t cnt) {
    asm volatile("mbarrier.init.shared.b64 [%0], %1;" :: "r"(mbar), "r"(cnt) : "memory");
}
__device__ __forceinline__ void mbar_expect_tx(uint32_t mbar, uint32_t bytes) {
    asm volatile("mbarrier.arrive.expect_tx.shared.b64 _, [%0], %1;"
                 :: "r"(mbar), "r"(bytes) : "memory");
}
__device__ __forceinline__ void bulk_g2s(uint32_t dst, const void* src,
                                         uint32_t bytes, uint32_t mbar) {
    asm volatile(
        "cp.async.bulk.shared::cta.global.mbarrier::complete_tx::bytes "
        "[%0], [%1], %2, [%3];"
        :: "r"(dst), "l"(src), "r"(bytes), "r"(mbar) : "memory");
}
__device__ __forceinline__ void mbar_wait(uint32_t mbar, uint32_t phase) {
    uint32_t done;
    do {
        asm volatile(
            "{\n\t.reg .pred p;\n\t"
            "mbarrier.try_wait.parity.acquire.cta.shared::cta.b64 p, [%1], %2, 0x989680;\n\t"
            "selp.b32 %0, 1, 0, p;\n\t}"
            : "=r"(done) : "r"(mbar), "r"(phase) : "memory");
    } while (!done);
}

// ---------- prep: fp16-pack weights into B-frag chunk stream -----------------
__global__ void mnre_prep(const float* __restrict__ W1t, const float* __restrict__ W1x,
                          const float* __restrict__ Wh) {
    const int blk = blockIdx.x;              // e*CPE + cg
    const int e  = blk / CPE;
    const int cg = blk % CPE;
    uint32_t* dst = wscratch + (size_t)blk * CHUNK_U32;
    for (int f = threadIdx.x; f < CHUNK_U32; f += blockDim.x) {
        const int col  = f >> 3;
        const int q    = f & 7;
        const int t    = q >> 1;
        const int half = q & 1;
        const int koff = half * 8 + t * 2;
        float v0, v1;
        if (cg < 18) {
            const int k = cg * BK + koff;
            auto ld = [&](int kk) -> float {
                return (kk < Tn) ? W1t[(size_t)(e * Tn + kk) * Hn + col]
                                 : W1x[(size_t)(e * Xn + (kk - Tn)) * Hn + col];
            };
            v0 = ld(k); v1 = ld(k + 1);
        } else {
            const int l = (cg < 50) ? 0 : 1;
            const int k = ((cg < 50) ? (cg - 18) : (cg - 50)) * BK + koff;
            const float* W = Wh + ((size_t)(l * En + e) * Hn + k) * Hn + col;
            v0 = W[0]; v1 = W[Hn];
        }
        dst[f] = pack_h2(v0, v1);
    }
}

// ---------- main fused kernel ------------------------------------------------
__global__ __launch_bounds__(NT, 2)
void mnre_h16p(const float* __restrict__ theta, const float* __restrict__ x,
               const int*   __restrict__ masks,
               const float* __restrict__ b1,  const float* __restrict__ a1,
               const float* __restrict__ bh,  const float* __restrict__ ah,
               const float* __restrict__ Wo,  const float* __restrict__ bo,
               float* __restrict__ out)
{
    extern __shared__ uint32_t smem[];
    uint32_t* abuf = smem;                 // A-frag-packed fp16 activations
    uint32_t* wrg  = smem + ABUF_U32;      // ST x CHUNK_U32 weight ring
    __shared__ alignas(8) unsigned long long mbars[ST];

    const int e    = blockIdx.y;
    const int m0   = blockIdx.x * BM;
    const int tid  = threadIdx.x;
    const int lane = tid & 31;
    const int wy   = tid >> 5;         // warpN 0..7
    const int g    = lane >> 2;        // 0..7
    const int t    = lane & 3;         // 0..3
    const int nbase = wy * 64;

    uint32_t bars[ST];
    #pragma unroll
    for (int i = 0; i < ST; i++)
        bars[i] = (uint32_t)__cvta_generic_to_shared(&mbars[i]);
    const uint32_t* wexp = wscratch + (size_t)e * CPE * CHUNK_U32;
    const uint32_t wrg0 = (uint32_t)__cvta_generic_to_shared(wrg);

    if (tid == 0) {
        #pragma unroll
        for (int i = 0; i < ST; i++) mbar_init(bars[i], 1);
        asm volatile("fence.proxy.async.shared::cta;" ::: "memory");
    }
    __syncthreads();

    // prologue: chunks 0,1 in flight
    if (tid == 0) {
        #pragma unroll
        for (int i = 0; i < 2; i++) {
            mbar_expect_tx(bars[i], CHUNK_BYTES);
            bulk_g2s(wrg0 + i * CHUNK_BYTES, wexp + (size_t)i * CHUNK_U32,
                     CHUNK_BYTES, bars[i]);
        }
    }

    // ---- stage inputs (fp16) into A-frag-packed abuf
    __half* hbuf = reinterpret_cast<__half*>(abuf);
    #pragma unroll
    for (int it = 0; it < (BM * Tn) / NT; it++) {
        const int i = tid + it * NT;
        const int m = i >> 5, k = i & 31;
        const float v = theta[(size_t)(m0 + m) * Tn + k] * (float)masks[e * Tn + k];
        hbuf[hidx(m, k)] = __float2half_rn(v);
    }
    #pragma unroll 4
    for (int it = 0; it < (BM * Xn) / NT; it++) {
        const int i = tid + it * NT;
        const int m = i >> 8, k = i & 255;
        hbuf[hidx(m, Tn + k)] = __float2half_rn(x[(size_t)(m0 + m) * Xn + k]);
    }

    float c[2][8][4];   // [mtile][nblock][frag]
    int qg = 0;         // global chunk index 0..CPE-1

    for (int layer = 0; layer < 1 + Ln; layer++) {
        const int K   = (layer == 0) ? (Tn + Xn) : Hn;
        const int nch = K / BK;            // 18 / 32 / 32 — all even
        const float* bias;
        const float* slope;
        if (layer == 0) {
            bias  = b1 + (size_t)e * Hn;
            slope = a1 + (size_t)e * Hn;
        } else {
            const int l = layer - 1;
            bias  = bh + (size_t)(l * En + e) * Hn;
            slope = ah + (size_t)(l * En + e) * Hn;
        }

        // init accumulators with bias
        #pragma unroll
        for (int nb = 0; nb < 8; nb++) {
            const int col0 = nbase + nb * 8 + 2 * t;
            const float bv0 = bias[col0], bv1 = bias[col0 + 1];
            #pragma unroll
            for (int mt = 0; mt < 2; mt++) {
                c[mt][nb][0] = bv0; c[mt][nb][1] = bv1;
                c[mt][nb][2] = bv0; c[mt][nb][3] = bv1;
            }
        }

        for (int ci = 0; ci < nch; ci += 2, qg += 2) {
            __syncthreads();   // all warps done with the stages being refilled

            // prefetch the next pair (stages freed by the previous iteration)
            if (tid == 0) {
                #pragma unroll
                for (int u = 2; u < 4; u++) {
                    const int p = qg + u;
                    if (p < CPE) {
                        const int sn = p & (ST - 1);
                        mbar_expect_tx(bars[sn], CHUNK_BYTES);
                        bulk_g2s(wrg0 + sn * CHUNK_BYTES,
                                 wexp + (size_t)p * CHUNK_U32, CHUNK_BYTES, bars[sn]);
                    }
                }
            }

            #pragma unroll
            for (int u = 0; u < 2; u++) {
                const int q  = qg + u;
                const int sc = q & (ST - 1);
                mbar_wait(bars[sc], (q >> 2) & 1u);
                const uint32_t* w = wrg + sc * CHUNK_U32;
                const int k16 = ci + u;

                // A frags: one LDS.128 per m16 tile (4 HMMA A-regs)
                uint32_t a[2][4];
                #pragma unroll
                for (int mt = 0; mt < 2; mt++) {
                    const uint4 av = *reinterpret_cast<const uint4*>(
                        abuf + ((k16 * 2 + mt) * 32 + lane) * 4);
                    a[mt][0] = av.x; a[mt][1] = av.y; a[mt][2] = av.z; a[mt][3] = av.w;
                }
                // B frags: one LDS.64 per nb (2 HMMA B-regs)
                #pragma unroll
                for (int nb = 0; nb < 8; nb++) {
                    const int col = nbase + nb * 8 + g;
                    const uint2 bv = *reinterpret_cast<const uint2*>(
                        w + (col * 4 + t) * 2);
                    mma_f16(c[0][nb], a[0][0], a[0][1], a[0][2], a[0][3], bv.x, bv.y);
                    mma_f16(c[1][nb], a[1][0], a[1][1], a[1][2], a[1][3], bv.x, bv.y);
                }
            }
        }

        __syncthreads();   // all abuf reads for this layer done
        // epilogue: PReLU, fp16-pack, write A-frag-packed (in place)
        #pragma unroll
        for (int nb = 0; nb < 8; nb++) {
            const int col0 = nbase + nb * 8 + 2 * t;
            const float s0 = slope[col0], s1 = slope[col0 + 1];
            const int kb = wy * 4 + (nb >> 1);
            const int h  = nb & 1;
            #pragma unroll
            for (int mt = 0; mt < 2; mt++) {
                float v0 = c[mt][nb][0]; v0 = (v0 >= 0.f) ? v0 : s0 * v0;
                float v1 = c[mt][nb][1]; v1 = (v1 >= 0.f) ? v1 : s1 * v1;
                float v2 = c[mt][nb][2]; v2 = (v2 >= 0.f) ? v2 : s0 * v2;
                float v3 = c[mt][nb][3]; v3 = (v3 >= 0.f) ? v3 : s1 * v3;
                uint2 o;
                o.x = pack_h2(v0, v1);   // row g     (a0/a2 slot)
                o.y = pack_h2(v2, v3);   // row g + 8 (a1/a3 slot)
                *reinterpret_cast<uint2*>(
                    abuf + (kb * 2 + mt) * 128 + (g * 4 + t) * 4 + 2 * h) = o;
            }
        }
    }
    __syncthreads();

    // ---- output: dot with Wo, shfl reduce (fp32)
    {
        const float* wo = Wo + (size_t)e * Hn;
        const int r0 = wy * 4;   // 8 warps x 4 rows = 32
        float partial[4] = {0.f, 0.f, 0.f, 0.f};
        #pragma unroll
        for (int j = 0; j < 16; j++) {
            const int cidx = lane + j * 32;
            const float wv = wo[cidx];
            #pragma unroll
            for (int r = 0; r < 4; r++)
                partial[r] = fmaf(__half2float(hbuf[hidx(r0 + r, cidx)]), wv, partial[r]);
        }
        const float bov = bo[e];
        #pragma unroll
        for (int r = 0; r < 4; r++) {
            float s = partial[r];
            #pragma unroll
            for (int off = 16; off > 0; off >>= 1)
                s += __shfl_xor_sync(0xffffffffu, s, off);
            if (lane == 0)
                out[(size_t)(m0 + r0 + r) * En + e] = s + bov;
        }
    }
}

extern "C" void kernel_launch(void* const* d_in, const int* in_sizes, int n_in,
                              void* d_out, int out_size) {
    const float* theta = (const float*)d_in[0];
    const float* x     = (const float*)d_in[1];
    const int*   masks = (const int*)  d_in[2];
    const float* W1t   = (const float*)d_in[3];
    const float* W1x   = (const float*)d_in[4];
    const float* b1    = (const float*)d_in[5];
    const float* a1    = (const float*)d_in[6];
    const float* Wh    = (const float*)d_in[7];
    const float* bh    = (const float*)d_in[8];
    const float* ah    = (const float*)d_in[9];
    const float* Wo    = (const float*)d_in[10];
    const float* bo    = (const float*)d_in[11];
    float* out = (float*)d_out;

    // 1) fp16-pack weights into the B-frag chunk stream
    mnre_prep<<<En * CPE, 256>>>(W1t, W1x, Wh);

    // 2) fused fp16-HMMA MLP, BM=32, 2 CTAs/SM, paired chunk iterations
    cudaFuncSetAttribute(mnre_h16p, cudaFuncAttributeMaxDynamicSharedMemorySize,
                         SMEM_BYTES);
    dim3 grid(Bn / BM, En);   // 128 x 32 = 4096 CTAs
    mnre_h16p<<<grid, NT, SMEM_BYTES>>>(theta, x, masks, b1, a1,
                                        bh, ah, Wo, bo, out);
}